// round 1
// baseline (speedup 1.0000x reference)
#include <cuda_runtime.h>
#include <cuda_bf16.h>
#include <math.h>

// Problem shape (fixed by reference)
#define BATCH 32
#define LDIM  512
#define DDIM  768
#define EPSF  1e-5f

// Tiling
#define BM 128
#define BN 128
#define BK 16
#define TILES_D (DDIM / BM)            // 6
#define NPAIRS  (TILES_D * (TILES_D + 1) / 2)  // 21

// Scratch: per-token weights (no cudaMalloc allowed)
__device__ float g_w[BATCH * LDIM];

// ---------------------------------------------------------------------------
// Kernel 1: w[b,l] = sqrt(eps + sum_d x[b,l,d]^2)
// One warp per row; block = 8 warps.
// ---------------------------------------------------------------------------
__global__ void weight_kernel(const float* __restrict__ x) {
    int row = blockIdx.x * 8 + threadIdx.y;   // 0 .. BATCH*LDIM-1
    const float* p = x + (size_t)row * DDIM;
    float s = 0.f;
    #pragma unroll
    for (int i = threadIdx.x; i < DDIM; i += 32) {
        float v = p[i];
        s = fmaf(v, v, s);
    }
    #pragma unroll
    for (int o = 16; o > 0; o >>= 1) s += __shfl_xor_sync(0xffffffffu, s, o);
    if (threadIdx.x == 0) g_w[row] = sqrtf(EPSF + s);
}

// ---------------------------------------------------------------------------
// Kernel 2: C[b] = (diag(w) X)^T X, exploiting symmetry.
// 128x128 output tile per block, 256 threads, 8x8 micro-tile per thread.
// Upper-triangular tile pairs only; off-diagonal tiles are mirrored on store.
// ---------------------------------------------------------------------------
__global__ __launch_bounds__(256, 2)
void gram_kernel(const float* __restrict__ X, float* __restrict__ C) {
    int p = blockIdx.x % NPAIRS;
    int b = blockIdx.x / NPAIRS;

    // map p -> (ti, tj) with tj >= ti
    int ti = 0, rem = p;
    while (rem >= TILES_D - ti) { rem -= TILES_D - ti; ti++; }
    int tj = ti + rem;
    int m0 = ti * BM;
    int n0 = tj * BN;

    const float* __restrict__ Xb = X + (size_t)b * LDIM * DDIM;
    float* __restrict__ Cb = C + (size_t)b * DDIM * DDIM;
    const float* __restrict__ wb = g_w + b * LDIM;

    __shared__ float As[BK][BM];   // A[k][m] = w[k]*X[k][m0+m]
    __shared__ float Bs[BK][BN];   // B[k][n] = X[k][n0+n]

    int tid = threadIdx.x;
    int tx = tid & 15;        // 0..15  -> n direction
    int ty = tid >> 4;        // 0..15  -> m direction

    float acc[8][8];
    #pragma unroll
    for (int i = 0; i < 8; i++)
        #pragma unroll
        for (int j = 0; j < 8; j++) acc[i][j] = 0.f;

    float af[8], bf[8];

    for (int kt = 0; kt < LDIM; kt += BK) {
        // --- fill SMEM: 2048 floats per tile = 512 float4; 256 threads x 2 ---
        #pragma unroll
        for (int i = 0; i < 2; i++) {
            int li = tid + i * 256;          // float4 slot 0..511
            int r  = li >> 5;                // row in k (0..15)
            int c  = (li & 31) << 2;         // col (0,4,...,124)
            const float* src = Xb + (size_t)(kt + r) * DDIM;
            float w = wb[kt + r];
            float4 va = *(const float4*)(src + m0 + c);
            va.x *= w; va.y *= w; va.z *= w; va.w *= w;
            *(float4*)(&As[r][c]) = va;
            float4 vb = *(const float4*)(src + n0 + c);
            *(float4*)(&Bs[r][c]) = vb;
        }
        __syncthreads();

        #pragma unroll
        for (int kk = 0; kk < BK; kk++) {
            *(float4*)(&af[0]) = *(const float4*)(&As[kk][ty * 8]);
            *(float4*)(&af[4]) = *(const float4*)(&As[kk][ty * 8 + 4]);
            *(float4*)(&bf[0]) = *(const float4*)(&Bs[kk][tx * 8]);
            *(float4*)(&bf[4]) = *(const float4*)(&Bs[kk][tx * 8 + 4]);
            #pragma unroll
            for (int i = 0; i < 8; i++)
                #pragma unroll
                for (int j = 0; j < 8; j++)
                    acc[i][j] = fmaf(af[i], bf[j], acc[i][j]);
        }
        __syncthreads();
    }

    // --- store direct block C[m, n] ---
    #pragma unroll
    for (int i = 0; i < 8; i++) {
        int m = m0 + ty * 8 + i;
        float* cp = Cb + (size_t)m * DDIM + n0 + tx * 8;
        float4 v0 = make_float4(acc[i][0], acc[i][1], acc[i][2], acc[i][3]);
        float4 v1 = make_float4(acc[i][4], acc[i][5], acc[i][6], acc[i][7]);
        *(float4*)(cp)     = v0;
        *(float4*)(cp + 4) = v1;
    }

    // --- mirrored block C[n, m] for off-diagonal tiles ---
    if (ti != tj) {
        #pragma unroll
        for (int j = 0; j < 8; j++) {
            int n = n0 + tx * 8 + j;
            float* cp = Cb + (size_t)n * DDIM + m0 + ty * 8;
            float4 v0 = make_float4(acc[0][j], acc[1][j], acc[2][j], acc[3][j]);
            float4 v1 = make_float4(acc[4][j], acc[5][j], acc[6][j], acc[7][j]);
            *(float4*)(cp)     = v0;
            *(float4*)(cp + 4) = v1;
        }
    }
}

// ---------------------------------------------------------------------------
extern "C" void kernel_launch(void* const* d_in, const int* in_sizes, int n_in,
                              void* d_out, int out_size) {
    const float* x = (const float*)d_in[0];
    float* out = (float*)d_out;

    // 1) per-token weights
    weight_kernel<<<(BATCH * LDIM) / 8, dim3(32, 8)>>>(x);

    // 2) weighted Gram (symmetric, upper-triangular tiles)
    gram_kernel<<<BATCH * NPAIRS, 256>>>(x, out);
}

// round 4
// speedup vs baseline: 2.3433x; 2.3433x over previous
#include <cuda_runtime.h>
#include <cuda_bf16.h>
#include <math.h>
#include <stdint.h>

// Problem shape
#define BATCH 32
#define LDIM  512
#define DDIM  768
#define EPSF  1e-5f

#define TILES_D 6
#define NPAIRS  21                 // upper-triangular 128x128 tile pairs
#define BK      16                 // k per stage
#define NCHUNK  (LDIM / BK)        // 32
#define SAP     136                // smem row stride in floats (136 mod 32 = 8 -> conflict-free frags)
#define TILE_FLOATS (BK * SAP)     // 2176

// Scratch (no cudaMalloc allowed)
__device__ float g_w[BATCH * LDIM];

__device__ __forceinline__ float to_tf32(float f) {
    uint32_t u;
    asm("cvt.rna.tf32.f32 %0, %1;" : "=r"(u) : "f"(f));
    return __uint_as_float(u);
}

__device__ __forceinline__ void mma_tf32(float* c, const float* a, const float* b) {
    asm volatile(
        "mma.sync.aligned.m16n8k8.row.col.f32.tf32.tf32.f32 "
        "{%0,%1,%2,%3}, {%4,%5,%6,%7}, {%8,%9}, {%0,%1,%2,%3};"
        : "+f"(c[0]), "+f"(c[1]), "+f"(c[2]), "+f"(c[3])
        : "r"(__float_as_uint(a[0])), "r"(__float_as_uint(a[1])),
          "r"(__float_as_uint(a[2])), "r"(__float_as_uint(a[3])),
          "r"(__float_as_uint(b[0])), "r"(__float_as_uint(b[1])));
}

// ---------------------------------------------------------------------------
// Kernel 1: w[b,l] = sqrt(eps + sum_d x^2)
// ---------------------------------------------------------------------------
__global__ void weight_kernel(const float* __restrict__ x) {
    int row = blockIdx.x * 8 + threadIdx.y;
    const float* p = x + (size_t)row * DDIM;
    float s = 0.f;
    #pragma unroll
    for (int i = threadIdx.x; i < DDIM; i += 32) {
        float v = p[i];
        s = fmaf(v, v, s);
    }
    #pragma unroll
    for (int o = 16; o > 0; o >>= 1) s += __shfl_xor_sync(0xffffffffu, s, o);
    if (threadIdx.x == 0) g_w[row] = sqrtf(EPSF + s);
}

// ---------------------------------------------------------------------------
// Kernel 2: tf32 tensor-core weighted Gram.
// Block: 128x128 C tile; 8 warps in 2(m) x 4(n); warp tile 64x32.
// SMEM: double-buffered k-major tiles As[k][m] (w-scaled), Bs[k][n].
// ---------------------------------------------------------------------------
__global__ __launch_bounds__(256, 2)
void gram_tc_kernel(const float* __restrict__ X, float* __restrict__ C) {
    __shared__ float sm[2][2][TILE_FLOATS];   // [stage][A/B][k*SAP+col]

    int p = blockIdx.x % NPAIRS;
    int b = blockIdx.x / NPAIRS;
    int ti = 0, rem = p;
    while (rem >= TILES_D - ti) { rem -= TILES_D - ti; ti++; }
    int tj = ti + rem;
    int m0 = ti * 128, n0 = tj * 128;

    const float* __restrict__ Xb = X + (size_t)b * LDIM * DDIM;
    float* __restrict__ Cb = C + (size_t)b * DDIM * DDIM;
    const float* __restrict__ wb = g_w + b * LDIM;

    int tid  = threadIdx.x;
    int wid  = tid >> 5, lane = tid & 31;
    int g = lane >> 2, t = lane & 3;
    int wm = (wid & 1) * 64;
    int wn = (wid >> 1) * 32;

    // Fill slots: j = tid + i*256 over 512 float4 per tile; k = j>>5, mseg = j&31
    int k_s[2], c_s[2];
    #pragma unroll
    for (int i = 0; i < 2; i++) {
        int j = tid + i * 256;
        k_s[i] = j >> 5;
        c_s[i] = (j & 31) * 4;
    }

    float acc[4][4][4];
    #pragma unroll
    for (int i = 0; i < 4; i++)
        #pragma unroll
        for (int j = 0; j < 4; j++)
            #pragma unroll
            for (int r = 0; r < 4; r++) acc[i][j][r] = 0.f;

    float4 ba[2], bb[2];
    float  wv[2];

    // fetch chunk kt into regs (A scaled by w, both tf32-rounded)
    auto FETCH = [&](int kt) {
        #pragma unroll
        for (int i = 0; i < 2; i++) {
            const float* src = Xb + (size_t)(kt + k_s[i]) * DDIM;
            wv[i] = wb[kt + k_s[i]];
            ba[i] = *(const float4*)(src + m0 + c_s[i]);
            bb[i] = *(const float4*)(src + n0 + c_s[i]);
        }
    };
    auto STORE = [&](int s) {
        #pragma unroll
        for (int i = 0; i < 2; i++) {
            float* da = &sm[s][0][k_s[i] * SAP + c_s[i]];
            float* db = &sm[s][1][k_s[i] * SAP + c_s[i]];
            da[0] = to_tf32(ba[i].x * wv[i]);
            da[1] = to_tf32(ba[i].y * wv[i]);
            da[2] = to_tf32(ba[i].z * wv[i]);
            da[3] = to_tf32(ba[i].w * wv[i]);
            db[0] = to_tf32(bb[i].x);
            db[1] = to_tf32(bb[i].y);
            db[2] = to_tf32(bb[i].z);
            db[3] = to_tf32(bb[i].w);
        }
    };

    FETCH(0);
    STORE(0);
    __syncthreads();

    for (int c = 0; c < NCHUNK; c++) {
        int s = c & 1;
        if (c + 1 < NCHUNK) FETCH((c + 1) * BK);

        const float* As = &sm[s][0][0];
        const float* Bs = &sm[s][1][0];
        #pragma unroll
        for (int kk = 0; kk < BK; kk += 8) {
            float afr[4][4];
            #pragma unroll
            for (int i = 0; i < 4; i++) {
                int m = wm + 16 * i + g;
                afr[i][0] = As[(kk + t) * SAP + m];
                afr[i][1] = As[(kk + t) * SAP + m + 8];
                afr[i][2] = As[(kk + t + 4) * SAP + m];
                afr[i][3] = As[(kk + t + 4) * SAP + m + 8];
            }
            float bfr[4][2];
            #pragma unroll
            for (int j = 0; j < 4; j++) {
                int n = wn + 8 * j + g;
                bfr[j][0] = Bs[(kk + t) * SAP + n];
                bfr[j][1] = Bs[(kk + t + 4) * SAP + n];
            }
            #pragma unroll
            for (int i = 0; i < 4; i++)
                #pragma unroll
                for (int j = 0; j < 4; j++)
                    mma_tf32(acc[i][j], afr[i], bfr[j]);
        }

        __syncthreads();
        if (c + 1 < NCHUNK) {
            STORE(s ^ 1);
            __syncthreads();
        }
    }

    // Epilogue: direct tile
    #pragma unroll
    for (int i = 0; i < 4; i++) {
        #pragma unroll
        for (int j = 0; j < 4; j++) {
            int m = m0 + wm + 16 * i + g;
            int n = n0 + wn + 8 * j + 2 * t;
            *(float2*)(Cb + (size_t)m * DDIM + n) =
                make_float2(acc[i][j][0], acc[i][j][1]);
            *(float2*)(Cb + (size_t)(m + 8) * DDIM + n) =
                make_float2(acc[i][j][2], acc[i][j][3]);
        }
    }
    // Mirror for off-diagonal tile pairs
    if (ti != tj) {
        #pragma unroll
        for (int i = 0; i < 4; i++) {
            #pragma unroll
            for (int j = 0; j < 4; j++) {
                int m = m0 + wm + 16 * i + g;
                int n = n0 + wn + 8 * j + 2 * t;
                Cb[(size_t)n * DDIM + m]           = acc[i][j][0];
                Cb[(size_t)(n + 1) * DDIM + m]     = acc[i][j][1];
                Cb[(size_t)n * DDIM + m + 8]       = acc[i][j][2];
                Cb[(size_t)(n + 1) * DDIM + m + 8] = acc[i][j][3];
            }
        }
    }
}

// ---------------------------------------------------------------------------
extern "C" void kernel_launch(void* const* d_in, const int* in_sizes, int n_in,
                              void* d_out, int out_size) {
    const float* x = (const float*)d_in[0];
    float* out = (float*)d_out;

    weight_kernel<<<(BATCH * LDIM) / 8, dim3(32, 8)>>>(x);
    gram_tc_kernel<<<BATCH * NPAIRS, 256>>>(x, out);
}

// round 5
// speedup vs baseline: 3.3068x; 1.4112x over previous
#include <cuda_runtime.h>
#include <cuda_bf16.h>
#include <math.h>
#include <stdint.h>

// Problem shape
#define BATCH 32
#define LDIM  512
#define DDIM  768
#define EPSF  1e-5f

#define TILES_D 6
#define NPAIRS  21                 // upper-triangular 128x128 tile pairs
#define BK      16                 // k rows per stage
#define NCHUNK  (LDIM / BK)        // 32
#define STAGES  4
#define SAP     136                // smem row stride in floats (conflict-free fragments)
#define TILE_FLOATS (BK * SAP)     // 2176
#define SMEM_BYTES (STAGES * 2 * TILE_FLOATS * 4)   // 69632

// Scratch: pre-rounded, weight-folded copy of X (no cudaMalloc allowed)
__device__ float g_Z[BATCH * LDIM * DDIM];

__device__ __forceinline__ float to_tf32(float f) {
    uint32_t u;
    asm("cvt.rna.tf32.f32 %0, %1;" : "=r"(u) : "f"(f));
    return __uint_as_float(u);
}

__device__ __forceinline__ void cp16(void* sptr, const void* g) {
    uint32_t a = (uint32_t)__cvta_generic_to_shared(sptr);
    asm volatile("cp.async.cg.shared.global [%0], [%1], 16;" :: "r"(a), "l"(g));
}

__device__ __forceinline__ void mma_tf32(float* c, const float* a, const float* b) {
    asm volatile(
        "mma.sync.aligned.m16n8k8.row.col.f32.tf32.tf32.f32 "
        "{%0,%1,%2,%3}, {%4,%5,%6,%7}, {%8,%9}, {%0,%1,%2,%3};"
        : "+f"(c[0]), "+f"(c[1]), "+f"(c[2]), "+f"(c[3])
        : "r"(__float_as_uint(a[0])), "r"(__float_as_uint(a[1])),
          "r"(__float_as_uint(a[2])), "r"(__float_as_uint(a[3])),
          "r"(__float_as_uint(b[0])), "r"(__float_as_uint(b[1])));
}

// ---------------------------------------------------------------------------
// Kernel 1: Z[b,l,:] = rna_tf32( sqrt(sqrt(eps + ||x||^2)) * x[b,l,:] )
// One warp per row; each lane holds 6 float4 (768 floats/row).
// ---------------------------------------------------------------------------
__global__ void prep_kernel(const float* __restrict__ x) {
    int row  = blockIdx.x * 8 + threadIdx.y;       // 0 .. BATCH*LDIM-1
    int lane = threadIdx.x;
    const float4* p = (const float4*)(x + (size_t)row * DDIM);
    float4* z = (float4*)(g_Z + (size_t)row * DDIM);

    float4 v[6];
    float s = 0.f;
    #pragma unroll
    for (int i = 0; i < 6; i++) {
        v[i] = p[lane + i * 32];
        s = fmaf(v[i].x, v[i].x, s);
        s = fmaf(v[i].y, v[i].y, s);
        s = fmaf(v[i].z, v[i].z, s);
        s = fmaf(v[i].w, v[i].w, s);
    }
    #pragma unroll
    for (int o = 16; o > 0; o >>= 1) s += __shfl_xor_sync(0xffffffffu, s, o);
    s = __shfl_sync(0xffffffffu, s, 0);
    float sw = sqrtf(sqrtf(EPSF + s));             // sqrt(w)

    #pragma unroll
    for (int i = 0; i < 6; i++) {
        float4 o4;
        o4.x = to_tf32(v[i].x * sw);
        o4.y = to_tf32(v[i].y * sw);
        o4.z = to_tf32(v[i].z * sw);
        o4.w = to_tf32(v[i].w * sw);
        z[lane + i * 32] = o4;
    }
}

// ---------------------------------------------------------------------------
// Kernel 2: C[b] tile = Z_m^T Z_n via tf32 mma.sync, 4-stage cp.async pipeline.
// 8 warps in 2(m) x 4(n), warp tile 64x32, 128x128 CTA tile, symmetry mirror.
// ---------------------------------------------------------------------------
extern __shared__ float smf[];

__global__ __launch_bounds__(256, 2)
void gram_tc_kernel(float* __restrict__ C) {
    int p = blockIdx.x % NPAIRS;
    int b = blockIdx.x / NPAIRS;
    int ti = 0, rem = p;
    while (rem >= TILES_D - ti) { rem -= TILES_D - ti; ti++; }
    int tj = ti + rem;
    int m0 = ti * 128, n0 = tj * 128;

    const float* __restrict__ Zb = g_Z + (size_t)b * LDIM * DDIM;
    float* __restrict__ Cb = C + (size_t)b * DDIM * DDIM;

    int tid  = threadIdx.x;
    int wid  = tid >> 5, lane = tid & 31;
    int g = lane >> 2, t = lane & 3;
    int wm = (wid & 1) * 64;
    int wn = (wid >> 1) * 32;

    // Two load slots per thread cover one 16x128 tile (512 float4 slots)
    const float* gA[2]; const float* gB[2]; int soff[2];
    #pragma unroll
    for (int i = 0; i < 2; i++) {
        int j = tid + i * 256;
        int ks = j >> 5;             // k row 0..15
        int cs = (j & 31) * 4;       // col 0,4,...,124
        gA[i] = Zb + (size_t)ks * DDIM + m0 + cs;
        gB[i] = Zb + (size_t)ks * DDIM + n0 + cs;
        soff[i] = ks * SAP + cs;
    }

    auto ISSUE = [&](int chunk) {
        float* base = smf + (chunk % STAGES) * 2 * TILE_FLOATS;
        size_t go = (size_t)chunk * BK * DDIM;
        #pragma unroll
        for (int i = 0; i < 2; i++) {
            cp16(base + soff[i],               gA[i] + go);
            cp16(base + TILE_FLOATS + soff[i], gB[i] + go);
        }
    };

    // Prologue: stages 0..STAGES-2
    #pragma unroll
    for (int c = 0; c < STAGES - 1; c++) {
        ISSUE(c);
        asm volatile("cp.async.commit_group;" ::: "memory");
    }

    float acc[4][4][4];
    #pragma unroll
    for (int i = 0; i < 4; i++)
        #pragma unroll
        for (int j = 0; j < 4; j++)
            #pragma unroll
            for (int r = 0; r < 4; r++) acc[i][j][r] = 0.f;

    for (int c = 0; c < NCHUNK; c++) {
        asm volatile("cp.async.wait_group %0;" :: "n"(STAGES - 2) : "memory");
        __syncthreads();

        const float* As = smf + (c % STAGES) * 2 * TILE_FLOATS;
        const float* Bs = As + TILE_FLOATS;
        #pragma unroll
        for (int kk = 0; kk < BK; kk += 8) {
            float afr[4][4];
            #pragma unroll
            for (int i = 0; i < 4; i++) {
                int m = wm + 16 * i + g;
                afr[i][0] = As[(kk + t) * SAP + m];
                afr[i][1] = As[(kk + t) * SAP + m + 8];
                afr[i][2] = As[(kk + t + 4) * SAP + m];
                afr[i][3] = As[(kk + t + 4) * SAP + m + 8];
            }
            float bfr[4][2];
            #pragma unroll
            for (int j = 0; j < 4; j++) {
                int n = wn + 8 * j + g;
                bfr[j][0] = Bs[(kk + t) * SAP + n];
                bfr[j][1] = Bs[(kk + t + 4) * SAP + n];
            }
            #pragma unroll
            for (int i = 0; i < 4; i++)
                #pragma unroll
                for (int j = 0; j < 4; j++)
                    mma_tf32(acc[i][j], afr[i], bfr[j]);
        }

        if (c + STAGES - 1 < NCHUNK) ISSUE(c + STAGES - 1);
        asm volatile("cp.async.commit_group;" ::: "memory");   // empty group in tail keeps accounting uniform
    }

    // Epilogue: direct tile
    #pragma unroll
    for (int i = 0; i < 4; i++) {
        #pragma unroll
        for (int j = 0; j < 4; j++) {
            int m = m0 + wm + 16 * i + g;
            int n = n0 + wn + 8 * j + 2 * t;
            *(float2*)(Cb + (size_t)m * DDIM + n) =
                make_float2(acc[i][j][0], acc[i][j][1]);
            *(float2*)(Cb + (size_t)(m + 8) * DDIM + n) =
                make_float2(acc[i][j][2], acc[i][j][3]);
        }
    }
    // Mirror for off-diagonal tile pairs
    if (ti != tj) {
        #pragma unroll
        for (int i = 0; i < 4; i++) {
            #pragma unroll
            for (int j = 0; j < 4; j++) {
                int m = m0 + wm + 16 * i + g;
                int n = n0 + wn + 8 * j + 2 * t;
                Cb[(size_t)n * DDIM + m]           = acc[i][j][0];
                Cb[(size_t)(n + 1) * DDIM + m]     = acc[i][j][1];
                Cb[(size_t)n * DDIM + m + 8]       = acc[i][j][2];
                Cb[(size_t)(n + 1) * DDIM + m + 8] = acc[i][j][3];
            }
        }
    }
}

// ---------------------------------------------------------------------------
extern "C" void kernel_launch(void* const* d_in, const int* in_sizes, int n_in,
                              void* d_out, int out_size) {
    const float* x = (const float*)d_in[0];
    float* out = (float*)d_out;

    static int configured = 0;
    if (!configured) {
        cudaFuncSetAttribute(gram_tc_kernel,
                             cudaFuncAttributeMaxDynamicSharedMemorySize, SMEM_BYTES);
        configured = 1;
    }

    prep_kernel<<<(BATCH * LDIM) / 8, dim3(32, 8)>>>(x);
    gram_tc_kernel<<<BATCH * NPAIRS, 256, SMEM_BYTES>>>(out);
}